// round 8
// baseline (speedup 1.0000x reference)
#include <cuda_runtime.h>
#include <cuda_fp16.h>
#include <cstdint>

// ---------------------------------------------------------------------------
// DCGN collapses (normalized adjacency == identity) to:
//   g1 = node_conv(x, conv1_w)                [8192, 2048]
//   h  = lrelu(g1 @ prop1_W + prop1_B)        [8192, 1100]  (N pad -> 1152, fp16)
//   g2 = node_conv(h, conv2_w)                [2048, 1100]  (K pad -> 1152)
//   out= lrelu(g2 @ prop2_W + prop2_B)        [2048, 512]
// Both GEMMs: plain fp16 x fp16 mma.sync (measured error budget ~3e-5)
// GEMM: 128x128 CTA, 4 warps of 64x64, BK=32, 4-stage cp.async, 2 CTA/SM,
// loop-invariant swizzled offsets precomputed, mainloop unrolled x4.
// ---------------------------------------------------------------------------

#define ROWS1 8192
#define F1    2048
#define N1R   1100
#define N1P   1152
#define ROWS2 2048
#define K2P   1152
#define N2    512

__device__ __half g_g1[(size_t)ROWS1 * F1];
__device__ __half g_h [(size_t)ROWS1 * N1P];
__device__ __half g_g2[(size_t)ROWS2 * K2P];
__device__ __half g_w1[(size_t)N1P * F1];
__device__ __half g_w2[(size_t)N2 * K2P];

// ===================== PTX helpers ========================

__device__ __forceinline__ uint32_t smem_u32(const void* p) {
    uint32_t a;
    asm("{ .reg .u64 t; cvta.to.shared.u64 t, %1; cvt.u32.u64 %0, t; }"
        : "=r"(a) : "l"(p));
    return a;
}

__device__ __forceinline__ void cp16(uint32_t dst, const void* src) {
    asm volatile("cp.async.cg.shared.global [%0], [%1], 16;"
                 :: "r"(dst), "l"(src));
}

__device__ __forceinline__ void ldm_x4(uint32_t* r, uint32_t addr) {
    asm volatile("ldmatrix.sync.aligned.m8n8.x4.shared.b16 {%0,%1,%2,%3}, [%4];"
                 : "=r"(r[0]), "=r"(r[1]), "=r"(r[2]), "=r"(r[3]) : "r"(addr));
}

__device__ __forceinline__ void mma16816(float* c, const uint32_t* a,
                                         const uint32_t* b) {
    asm volatile(
        "mma.sync.aligned.m16n8k16.row.col.f32.f16.f16.f32 "
        "{%0,%1,%2,%3}, {%4,%5,%6,%7}, {%8,%9}, {%0,%1,%2,%3};"
        : "+f"(c[0]), "+f"(c[1]), "+f"(c[2]), "+f"(c[3])
        : "r"(a[0]), "r"(a[1]), "r"(a[2]), "r"(a[3]), "r"(b[0]), "r"(b[1]));
}

// swizzled byte offset inside a 128-row x 32-col fp16 tile (64B rows)
__device__ __forceinline__ uint32_t swz(uint32_t row, uint32_t chunk) {
    return row * 64u + ((chunk ^ ((row >> 1) & 3u)) << 4);
}

// ======================= prep kernels ======================================

// g = fp16(node_conv(x, w)), zero-padded to Kpad columns. InT = float|__half.
template <typename InT>
__global__ void nodeconv_fp16(const InT* __restrict__ x,
                              const float* __restrict__ w,   // [4, Freal]
                              __half* __restrict__ g,
                              int rows_out, int Freal, int Kpad, int in_stride)
{
    int idx = blockIdx.x * blockDim.x + threadIdx.x;
    int K4 = Kpad >> 2;
    if (idx >= rows_out * K4) return;
    int r = idx / K4;
    int c = (idx - r * K4) << 2;

    __align__(8) __half hv[4];
    if (c < Freal) {
        float acc[4] = {0.f, 0.f, 0.f, 0.f};
#pragma unroll
        for (int p = 0; p < 4; ++p) {
            float xv[4];
            if constexpr (sizeof(InT) == 4) {
                float4 t = *(const float4*)((const float*)x +
                                            (size_t)(4 * r + p) * in_stride + c);
                xv[0] = t.x; xv[1] = t.y; xv[2] = t.z; xv[3] = t.w;
            } else {
                uint2 t = *(const uint2*)((const __half*)x +
                                          (size_t)(4 * r + p) * in_stride + c);
                __half2 h0 = *(__half2*)&t.x, h1 = *(__half2*)&t.y;
                xv[0] = __low2float(h0);  xv[1] = __high2float(h0);
                xv[2] = __low2float(h1);  xv[3] = __high2float(h1);
            }
            float4 wv = *(const float4*)(w + (size_t)p * Freal + c);
            acc[0] = fmaf(xv[0], wv.x, acc[0]);
            acc[1] = fmaf(xv[1], wv.y, acc[1]);
            acc[2] = fmaf(xv[2], wv.z, acc[2]);
            acc[3] = fmaf(xv[3], wv.w, acc[3]);
        }
#pragma unroll
        for (int i = 0; i < 4; ++i) hv[i] = __float2half_rn(acc[i]);
    } else {
#pragma unroll
        for (int i = 0; i < 4; ++i) hv[i] = __float2half_rn(0.f);
    }
    *(uint2*)(g + (size_t)r * Kpad + c) = *(uint2*)hv;
}

// out[n,k] = fp16(W[k,n]), zero-padded
__global__ void transpose_fp16(const float* __restrict__ W,
                               __half* __restrict__ B,
                               int Kreal, int Kpad, int Nreal, int Npad)
{
    __shared__ float tile[32][33];
    int nb = blockIdx.x * 32, kb = blockIdx.y * 32;
    int tx = threadIdx.x, ty = threadIdx.y;  // (32, 8)
#pragma unroll
    for (int i = 0; i < 32; i += 8) {
        int k = kb + ty + i, n = nb + tx;
        tile[ty + i][tx] = (k < Kreal && n < Nreal) ? W[(size_t)k * Nreal + n] : 0.f;
    }
    __syncthreads();
#pragma unroll
    for (int i = 0; i < 32; i += 8) {
        int n = nb + ty + i, k = kb + tx;
        if (n < Npad && k < Kpad)
            B[(size_t)n * Kpad + k] = __float2half_rn(tile[tx][ty + i]);
    }
}

// ======================= fp16 mma.sync GEMM ================================
// C[M, ostride] (valid cols < Nreal) = lrelu(A @ B^T + bias)
// grid = (Npad/128, M/128), 128 threads (4 warps of 64x64), K % 128 == 0
// (so NC = K/32 is a multiple of 4 for the unrolled mainloop; both K=2048
// and K=1152 satisfy NC%4==0). OutT = __half or float.

#define BK       32
#define STAGES   4
#define TILE_B   8192                   // one 128x32 fp16 tile
#define STAGE_B  (2 * TILE_B)           // A + B
#define SMEM_DYN (STAGES * STAGE_B)     // 65536

template <typename OutT>
__global__ __launch_bounds__(128, 2)
void gemm_fp16(const __half* __restrict__ A,
               const __half* __restrict__ B,
               const float* __restrict__ bias,
               OutT* __restrict__ C,
               int K, int Nreal, int ostride)
{
    extern __shared__ __align__(1024) char smem[];
    const uint32_t sb = smem_u32(smem);

    const int tid  = threadIdx.x;
    const int wid  = tid >> 5;
    const int lane = tid & 31;
    const int row0 = blockIdx.y * 128;
    const int col0 = blockIdx.x * 128;
    const int NC   = K / BK;            // multiple of 4

    const int warp_m = (wid & 1) * 64;     // 2 warps in M
    const int warp_n = (wid >> 1) * 64;    // 2 warps in N

    // ---- cp.async: 4 chunks of 16B per thread per 128x32 tile ----
    // global row pointers precomputed once; per-issue adds kt*BK only.
    uint32_t ssw[4];
    const __half* pA[4];
    const __half* pB[4];
#pragma unroll
    for (int q = 0; q < 4; ++q) {
        const int idx = tid + q * 128;      // 0..511
        const int row = idx >> 2;
        ssw[q] = swz(row, idx & 3);
        const int kcol = (idx & 3) * 8;
        pA[q] = A + (size_t)(row0 + row) * K + kcol;
        pB[q] = B + (size_t)(col0 + row) * K + kcol;
    }

    auto issue_stage = [&](uint32_t base, int kt) {
        const int kb = kt * BK;
#pragma unroll
        for (int q = 0; q < 4; ++q) {
            cp16(base + ssw[q],          pA[q] + kb);
            cp16(base + TILE_B + ssw[q], pB[q] + kb);
        }
        asm volatile("cp.async.commit_group;");
    };

    // ---- loop-invariant swizzled ldmatrix offsets ----
    const uint32_t a_lrow = lane & 15;
    const uint32_t a_lchk = lane >> 4;
    const uint32_t b_lrow = (lane & 7) + ((lane >> 4) << 3);
    const uint32_t b_lchk = (lane >> 3) & 1;

    uint32_t off_a[2][4];   // [ks][mt]
    uint32_t off_b[2][4];   // [ks][ntp]  (+TILE_B folded in)
#pragma unroll
    for (int ks = 0; ks < 2; ++ks) {
#pragma unroll
        for (int t = 0; t < 4; ++t) {
            off_a[ks][t] = swz(warp_m + t * 16 + a_lrow, ks * 2 + a_lchk);
            off_b[ks][t] = swz(warp_n + t * 16 + b_lrow, ks * 2 + b_lchk)
                           + TILE_B;
        }
    }

    float acc[4][8][4];
#pragma unroll
    for (int mt = 0; mt < 4; ++mt)
#pragma unroll
        for (int nt = 0; nt < 8; ++nt)
#pragma unroll
            for (int q = 0; q < 4; ++q) acc[mt][nt][q] = 0.f;

    issue_stage(sb + 0 * STAGE_B, 0);
    issue_stage(sb + 1 * STAGE_B, 1);
    issue_stage(sb + 2 * STAGE_B, 2);

    // one unrolled-stage body; st is compile-time 0..3
    auto body = [&](int st, int i) {
        asm volatile("cp.async.wait_group 2;");
        __syncthreads();
        if (i + 3 < NC)
            issue_stage(sb + ((st + 3) & 3) * STAGE_B, i + 3);

        const uint32_t base = sb + st * STAGE_B;
#pragma unroll
        for (int ks = 0; ks < 2; ++ks) {
            uint32_t bfr[8][2];
#pragma unroll
            for (int ntp = 0; ntp < 4; ++ntp)
                ldm_x4(&bfr[ntp * 2][0], base + off_b[ks][ntp]);
#pragma unroll
            for (int mt = 0; mt < 4; ++mt) {
                uint32_t afr[4];
                ldm_x4(afr, base + off_a[ks][mt]);
#pragma unroll
                for (int nt = 0; nt < 8; ++nt)
                    mma16816(acc[mt][nt], afr, bfr[nt]);
            }
        }
    };

    for (int i = 0; i < NC; i += 4) {
        body(0, i);
        body(1, i + 1);
        body(2, i + 2);
        body(3, i + 3);
    }

    // ---- epilogue: bias + leaky relu ----
    const int erow = lane >> 2;
    const int ecol = (lane & 3) * 2;
#pragma unroll
    for (int mt = 0; mt < 4; ++mt) {
#pragma unroll
        for (int nt = 0; nt < 8; ++nt) {
            const int colg = col0 + warp_n + nt * 8 + ecol;
            if (colg >= Nreal) continue;
            const float bx = bias[colg], by = bias[colg + 1];
            const int rg0 = row0 + warp_m + mt * 16 + erow;
            float v0 = acc[mt][nt][0] + bx;
            float v1 = acc[mt][nt][1] + by;
            float v2 = acc[mt][nt][2] + bx;
            float v3 = acc[mt][nt][3] + by;
            v0 = (v0 >= 0.f) ? v0 : 0.01f * v0;
            v1 = (v1 >= 0.f) ? v1 : 0.01f * v1;
            v2 = (v2 >= 0.f) ? v2 : 0.01f * v2;
            v3 = (v3 >= 0.f) ? v3 : 0.01f * v3;
            if constexpr (sizeof(OutT) == 2) {
                *(__half2*)((__half*)C + (size_t)rg0 * ostride + colg) =
                    __floats2half2_rn(v0, v1);
                *(__half2*)((__half*)C + (size_t)(rg0 + 8) * ostride + colg) =
                    __floats2half2_rn(v2, v3);
            } else {
                *(float2*)((float*)C + (size_t)rg0 * ostride + colg) =
                    make_float2(v0, v1);
                *(float2*)((float*)C + (size_t)(rg0 + 8) * ostride + colg) =
                    make_float2(v2, v3);
            }
        }
    }
}

// ======================= launch ============================================

extern "C" void kernel_launch(void* const* d_in, const int* in_sizes, int n_in,
                              void* d_out, int out_size)
{
    const float* x       = (const float*)d_in[0];   // [64,512,2048]
    const float* conv1_w = (const float*)d_in[1];   // [4,2048]
    const float* prop1_W = (const float*)d_in[4];   // [2048,1100]
    const float* prop1_B = (const float*)d_in[5];   // [1100]
    const float* conv2_w = (const float*)d_in[6];   // [4,1100]
    const float* prop2_W = (const float*)d_in[9];   // [1100,512]
    const float* prop2_B = (const float*)d_in[10];  // [512]

    __half *g1, *g2, *w1, *w2, *h;
    cudaGetSymbolAddress((void**)&g1, g_g1);
    cudaGetSymbolAddress((void**)&h,  g_h);
    cudaGetSymbolAddress((void**)&g2, g_g2);
    cudaGetSymbolAddress((void**)&w1, g_w1);
    cudaGetSymbolAddress((void**)&w2, g_w2);

    cudaFuncSetAttribute((void*)gemm_fp16<__half>,
                         cudaFuncAttributeMaxDynamicSharedMemorySize, SMEM_DYN);
    cudaFuncSetAttribute((void*)gemm_fp16<float>,
                         cudaFuncAttributeMaxDynamicSharedMemorySize, SMEM_DYN);

    // weight transforms
    {
        dim3 blk(32, 8);
        transpose_fp16<<<dim3(N1P / 32, F1 / 32), blk>>>(prop1_W, w1,
                                                         F1, F1, N1R, N1P);
        transpose_fp16<<<dim3(N2 / 32, K2P / 32), blk>>>(prop2_W, w2,
                                                         N1R, K2P, N2, N2);
    }

    // stage 1
    {
        int total = ROWS1 * (F1 / 4);
        nodeconv_fp16<float><<<(total + 255) / 256, 256>>>(
            x, conv1_w, g1, ROWS1, F1, F1, F1);
        gemm_fp16<__half><<<dim3(N1P / 128, ROWS1 / 128), 128, SMEM_DYN>>>(
            g1, w1, prop1_B, h, F1, N1R, N1P);
    }

    // stage 2
    {
        int total = ROWS2 * (K2P / 4);
        nodeconv_fp16<__half><<<(total + 255) / 256, 256>>>(
            h, conv2_w, g2, ROWS2, N1R, K2P, N1P);
        gemm_fp16<float><<<dim3(N2 / 128, ROWS2 / 128), 128, SMEM_DYN>>>(
            g2, w2, prop2_B, (float*)d_out, K2P, N2, N2);
    }
}

// round 9
// speedup vs baseline: 1.0312x; 1.0312x over previous
#include <cuda_runtime.h>
#include <cuda_fp16.h>
#include <cstdint>

// ---------------------------------------------------------------------------
// DCGN collapses (normalized adjacency == identity) to:
//   g1 = node_conv(x, conv1_w)                [8192, 2048]
//   h  = lrelu(g1 @ prop1_W + prop1_B)        [8192, 1100]  (N pad -> 1152, fp16)
//   g2 = node_conv(h, conv2_w)                [2048, 1100]  (K pad -> 1152)
//   out= lrelu(g2 @ prop2_W + prop2_B)        [2048, 512]
// Both GEMMs: plain fp16 x fp16 mma.sync (measured error budget ~3e-5)
// GEMM: 128x128 CTA, 4 warps of 64x64, BK=32, 4-stage cp.async, 2 CTA/SM.
// R9: fragment software pipeline — all B frags loaded up front per iter,
// A frags double-buffered one (ks,mt) step ahead of their MMAs.
// ---------------------------------------------------------------------------

#define ROWS1 8192
#define F1    2048
#define N1R   1100
#define N1P   1152
#define ROWS2 2048
#define K2P   1152
#define N2    512

__device__ __half g_g1[(size_t)ROWS1 * F1];
__device__ __half g_h [(size_t)ROWS1 * N1P];
__device__ __half g_g2[(size_t)ROWS2 * K2P];
__device__ __half g_w1[(size_t)N1P * F1];
__device__ __half g_w2[(size_t)N2 * K2P];

// ===================== PTX helpers ========================

__device__ __forceinline__ uint32_t smem_u32(const void* p) {
    uint32_t a;
    asm("{ .reg .u64 t; cvta.to.shared.u64 t, %1; cvt.u32.u64 %0, t; }"
        : "=r"(a) : "l"(p));
    return a;
}

__device__ __forceinline__ void cp16(uint32_t dst, const void* src) {
    asm volatile("cp.async.cg.shared.global [%0], [%1], 16;"
                 :: "r"(dst), "l"(src));
}

__device__ __forceinline__ void ldm_x4(uint32_t* r, uint32_t addr) {
    asm volatile("ldmatrix.sync.aligned.m8n8.x4.shared.b16 {%0,%1,%2,%3}, [%4];"
                 : "=r"(r[0]), "=r"(r[1]), "=r"(r[2]), "=r"(r[3]) : "r"(addr));
}

__device__ __forceinline__ void mma16816(float* c, const uint32_t* a,
                                         const uint32_t* b) {
    asm volatile(
        "mma.sync.aligned.m16n8k16.row.col.f32.f16.f16.f32 "
        "{%0,%1,%2,%3}, {%4,%5,%6,%7}, {%8,%9}, {%0,%1,%2,%3};"
        : "+f"(c[0]), "+f"(c[1]), "+f"(c[2]), "+f"(c[3])
        : "r"(a[0]), "r"(a[1]), "r"(a[2]), "r"(a[3]), "r"(b[0]), "r"(b[1]));
}

// swizzled byte offset inside a 128-row x 32-col fp16 tile (64B rows)
__device__ __forceinline__ uint32_t swz(uint32_t row, uint32_t chunk) {
    return row * 64u + ((chunk ^ ((row >> 1) & 3u)) << 4);
}

// ======================= prep kernels ======================================

// g = fp16(node_conv(x, w)), zero-padded to Kpad columns. InT = float|__half.
template <typename InT>
__global__ void nodeconv_fp16(const InT* __restrict__ x,
                              const float* __restrict__ w,   // [4, Freal]
                              __half* __restrict__ g,
                              int rows_out, int Freal, int Kpad, int in_stride)
{
    int idx = blockIdx.x * blockDim.x + threadIdx.x;
    int K4 = Kpad >> 2;
    if (idx >= rows_out * K4) return;
    int r = idx / K4;
    int c = (idx - r * K4) << 2;

    __align__(8) __half hv[4];
    if (c < Freal) {
        float acc[4] = {0.f, 0.f, 0.f, 0.f};
#pragma unroll
        for (int p = 0; p < 4; ++p) {
            float xv[4];
            if constexpr (sizeof(InT) == 4) {
                float4 t = *(const float4*)((const float*)x +
                                            (size_t)(4 * r + p) * in_stride + c);
                xv[0] = t.x; xv[1] = t.y; xv[2] = t.z; xv[3] = t.w;
            } else {
                uint2 t = *(const uint2*)((const __half*)x +
                                          (size_t)(4 * r + p) * in_stride + c);
                __half2 h0 = *(__half2*)&t.x, h1 = *(__half2*)&t.y;
                xv[0] = __low2float(h0);  xv[1] = __high2float(h0);
                xv[2] = __low2float(h1);  xv[3] = __high2float(h1);
            }
            float4 wv = *(const float4*)(w + (size_t)p * Freal + c);
            acc[0] = fmaf(xv[0], wv.x, acc[0]);
            acc[1] = fmaf(xv[1], wv.y, acc[1]);
            acc[2] = fmaf(xv[2], wv.z, acc[2]);
            acc[3] = fmaf(xv[3], wv.w, acc[3]);
        }
#pragma unroll
        for (int i = 0; i < 4; ++i) hv[i] = __float2half_rn(acc[i]);
    } else {
#pragma unroll
        for (int i = 0; i < 4; ++i) hv[i] = __float2half_rn(0.f);
    }
    *(uint2*)(g + (size_t)r * Kpad + c) = *(uint2*)hv;
}

// out[n,k] = fp16(W[k,n]), zero-padded
__global__ void transpose_fp16(const float* __restrict__ W,
                               __half* __restrict__ B,
                               int Kreal, int Kpad, int Nreal, int Npad)
{
    __shared__ float tile[32][33];
    int nb = blockIdx.x * 32, kb = blockIdx.y * 32;
    int tx = threadIdx.x, ty = threadIdx.y;  // (32, 8)
#pragma unroll
    for (int i = 0; i < 32; i += 8) {
        int k = kb + ty + i, n = nb + tx;
        tile[ty + i][tx] = (k < Kreal && n < Nreal) ? W[(size_t)k * Nreal + n] : 0.f;
    }
    __syncthreads();
#pragma unroll
    for (int i = 0; i < 32; i += 8) {
        int n = nb + ty + i, k = kb + tx;
        if (n < Npad && k < Kpad)
            B[(size_t)n * Kpad + k] = __float2half_rn(tile[tx][ty + i]);
    }
}

// ======================= fp16 mma.sync GEMM ================================
// C[M, ostride] (valid cols < Nreal) = lrelu(A @ B^T + bias)
// grid = (Npad/128, M/128), 128 threads (4 warps of 64x64), K % 32 == 0,
// K/32 >= 4. OutT = __half or float.

#define BK       32
#define STAGES   4
#define TILE_B   8192                   // one 128x32 fp16 tile
#define STAGE_B  (2 * TILE_B)           // A + B
#define SMEM_DYN (STAGES * STAGE_B)     // 65536

template <typename OutT>
__global__ __launch_bounds__(128, 2)
void gemm_fp16(const __half* __restrict__ A,
               const __half* __restrict__ B,
               const float* __restrict__ bias,
               OutT* __restrict__ C,
               int K, int Nreal, int ostride)
{
    extern __shared__ __align__(1024) char smem[];
    const uint32_t sb = smem_u32(smem);

    const int tid  = threadIdx.x;
    const int wid  = tid >> 5;
    const int lane = tid & 31;
    const int row0 = blockIdx.y * 128;
    const int col0 = blockIdx.x * 128;
    const int NC   = K / BK;

    const int warp_m = (wid & 1) * 64;     // 2 warps in M
    const int warp_n = (wid >> 1) * 64;    // 2 warps in N

    // ---- cp.async mapping: thread covers 4 chunks per 128x32 tile ----
    uint32_t ssw[4];
    int      srow[4];
#pragma unroll
    for (int q = 0; q < 4; ++q) {
        const int idx = tid + q * 128;      // 0..511
        srow[q] = idx >> 2;
        ssw[q]  = swz(idx >> 2, idx & 3);
    }
    const int schk = tid & 3;

    auto issue_stage = [&](int st, int kt) {
        const int kb = kt * BK + schk * 8;
        const uint32_t base = sb + st * STAGE_B;
#pragma unroll
        for (int q = 0; q < 4; ++q) {
            cp16(base + ssw[q],          A + (size_t)(row0 + srow[q]) * K + kb);
            cp16(base + TILE_B + ssw[q], B + (size_t)(col0 + srow[q]) * K + kb);
        }
        asm volatile("cp.async.commit_group;");
    };

    float acc[4][8][4];
#pragma unroll
    for (int mt = 0; mt < 4; ++mt)
#pragma unroll
        for (int nt = 0; nt < 8; ++nt)
#pragma unroll
            for (int q = 0; q < 4; ++q) acc[mt][nt][q] = 0.f;

    issue_stage(0, 0);
    issue_stage(1, 1);
    issue_stage(2, 2);

    // ldmatrix lane-dependent pieces
    const uint32_t a_lrow = lane & 15;
    const uint32_t a_lchk = lane >> 4;
    const uint32_t b_lrow = (lane & 7) + ((lane >> 4) << 3);
    const uint32_t b_lchk = (lane >> 3) & 1;

    for (int i = 0; i < NC; ++i) {
        asm volatile("cp.async.wait_group 2;");
        __syncthreads();
        if (i + 3 < NC) issue_stage((i + 3) & 3, i + 3);

        const uint32_t base = sb + (i & 3) * STAGE_B;

        // ---- load ALL B fragments (both ks halves) up front ----
        uint32_t bfr[2][8][2];
#pragma unroll
        for (int ks = 0; ks < 2; ++ks)
#pragma unroll
            for (int ntp = 0; ntp < 4; ++ntp)
                ldm_x4(&bfr[ks][ntp * 2][0],
                       base + TILE_B +
                       swz(warp_n + ntp * 16 + b_lrow, ks * 2 + b_lchk));

        // ---- A fragments: double-buffered one step ahead ----
        uint32_t afr[2][4];
        ldm_x4(afr[0], base + swz(warp_m + a_lrow, a_lchk));
#pragma unroll
        for (int ks = 0; ks < 2; ++ks) {
#pragma unroll
            for (int mt = 0; mt < 4; ++mt) {
                const int step = ks * 4 + mt;
                const int cur  = step & 1;
                if (step < 7) {
                    const int nmt = (mt + 1) & 3;
                    const int nks = ks + (mt == 3 ? 1 : 0);
                    ldm_x4(afr[cur ^ 1],
                           base + swz(warp_m + nmt * 16 + a_lrow,
                                      nks * 2 + a_lchk));
                }
#pragma unroll
                for (int nt = 0; nt < 8; ++nt)
                    mma16816(acc[mt][nt], afr[cur], bfr[ks][nt]);
            }
        }
        // stage-reuse ordering is provided by the top-of-loop barrier
    }

    // ---- epilogue: bias + leaky relu ----
    const int erow = lane >> 2;
    const int ecol = (lane & 3) * 2;
#pragma unroll
    for (int mt = 0; mt < 4; ++mt) {
#pragma unroll
        for (int nt = 0; nt < 8; ++nt) {
            const int colg = col0 + warp_n + nt * 8 + ecol;
            if (colg >= Nreal) continue;
            const float bx = bias[colg], by = bias[colg + 1];
            const int rg0 = row0 + warp_m + mt * 16 + erow;
            float v0 = acc[mt][nt][0] + bx;
            float v1 = acc[mt][nt][1] + by;
            float v2 = acc[mt][nt][2] + bx;
            float v3 = acc[mt][nt][3] + by;
            v0 = (v0 >= 0.f) ? v0 : 0.01f * v0;
            v1 = (v1 >= 0.f) ? v1 : 0.01f * v1;
            v2 = (v2 >= 0.f) ? v2 : 0.01f * v2;
            v3 = (v3 >= 0.f) ? v3 : 0.01f * v3;
            if constexpr (sizeof(OutT) == 2) {
                *(__half2*)((__half*)C + (size_t)rg0 * ostride + colg) =
                    __floats2half2_rn(v0, v1);
                *(__half2*)((__half*)C + (size_t)(rg0 + 8) * ostride + colg) =
                    __floats2half2_rn(v2, v3);
            } else {
                *(float2*)((float*)C + (size_t)rg0 * ostride + colg) =
                    make_float2(v0, v1);
                *(float2*)((float*)C + (size_t)(rg0 + 8) * ostride + colg) =
                    make_float2(v2, v3);
            }
        }
    }
}

// ======================= launch ============================================

extern "C" void kernel_launch(void* const* d_in, const int* in_sizes, int n_in,
                              void* d_out, int out_size)
{
    const float* x       = (const float*)d_in[0];   // [64,512,2048]
    const float* conv1_w = (const float*)d_in[1];   // [4,2048]
    const float* prop1_W = (const float*)d_in[4];   // [2048,1100]
    const float* prop1_B = (const float*)d_in[5];   // [1100]
    const float* conv2_w = (const float*)d_in[6];   // [4,1100]
    const float* prop2_W = (const float*)d_in[9];   // [1100,512]
    const float* prop2_B = (const float*)d_in[10];  // [512]

    __half *g1, *g2, *w1, *w2, *h;
    cudaGetSymbolAddress((void**)&g1, g_g1);
    cudaGetSymbolAddress((void**)&h,  g_h);
    cudaGetSymbolAddress((void**)&g2, g_g2);
    cudaGetSymbolAddress((void**)&w1, g_w1);
    cudaGetSymbolAddress((void**)&w2, g_w2);

    cudaFuncSetAttribute((void*)gemm_fp16<__half>,
                         cudaFuncAttributeMaxDynamicSharedMemorySize, SMEM_DYN);
    cudaFuncSetAttribute((void*)gemm_fp16<float>,
                         cudaFuncAttributeMaxDynamicSharedMemorySize, SMEM_DYN);

    // weight transforms
    {
        dim3 blk(32, 8);
        transpose_fp16<<<dim3(N1P / 32, F1 / 32), blk>>>(prop1_W, w1,
                                                         F1, F1, N1R, N1P);
        transpose_fp16<<<dim3(N2 / 32, K2P / 32), blk>>>(prop2_W, w2,
                                                         N1R, K2P, N2, N2);
    }

    // stage 1
    {
        int total = ROWS1 * (F1 / 4);
        nodeconv_fp16<float><<<(total + 255) / 256, 256>>>(
            x, conv1_w, g1, ROWS1, F1, F1, F1);
        gemm_fp16<__half><<<dim3(N1P / 128, ROWS1 / 128), 128, SMEM_DYN>>>(
            g1, w1, prop1_B, h, F1, N1R, N1P);
    }

    // stage 2
    {
        int total = ROWS2 * (K2P / 4);
        nodeconv_fp16<__half><<<(total + 255) / 256, 256>>>(
            h, conv2_w, g2, ROWS2, N1R, K2P, N1P);
        gemm_fp16<float><<<dim3(N2 / 128, ROWS2 / 128), 128, SMEM_DYN>>>(
            g2, w2, prop2_B, (float*)d_out, K2P, N2, N2);
    }
}

// round 10
// speedup vs baseline: 1.0548x; 1.0229x over previous
#include <cuda_runtime.h>
#include <cuda_fp16.h>
#include <cstdint>

// ---------------------------------------------------------------------------
// DCGN collapses (normalized adjacency == identity) to:
//   g1 = node_conv(x, conv1_w)                [8192, 2048]
//   h  = lrelu(g1 @ prop1_W + prop1_B)        [8192, 1100]  (N pad -> 1152)
//   g2 = node_conv(h, conv2_w)                [2048, 1100]  (K pad -> 1152)
//   out= lrelu(g2 @ prop2_W + prop2_B)        [2048, 512]
// Both GEMMs: plain fp16 x fp16 mma.sync (measured error budget ~3e-5).
// R10: nodeconv2 FUSED into GEMM1's epilogue (h never materialized) —
// per-lane scale by conv2_w[row&3, col], shfl-reduce over 4-row windows,
// write g2 fp16 directly. GEMM core = R9 (best measured).
// ---------------------------------------------------------------------------

#define ROWS1 8192
#define F1    2048
#define N1R   1100
#define N1P   1152
#define ROWS2 2048
#define K2P   1152
#define N2    512

__device__ __half g_g1[(size_t)ROWS1 * F1];
__device__ __half g_g2[(size_t)ROWS2 * K2P];
__device__ __half g_w1[(size_t)N1P * F1];
__device__ __half g_w2[(size_t)N2 * K2P];

// ===================== PTX helpers ========================

__device__ __forceinline__ uint32_t smem_u32(const void* p) {
    uint32_t a;
    asm("{ .reg .u64 t; cvta.to.shared.u64 t, %1; cvt.u32.u64 %0, t; }"
        : "=r"(a) : "l"(p));
    return a;
}

__device__ __forceinline__ void cp16(uint32_t dst, const void* src) {
    asm volatile("cp.async.cg.shared.global [%0], [%1], 16;"
                 :: "r"(dst), "l"(src));
}

__device__ __forceinline__ void ldm_x4(uint32_t* r, uint32_t addr) {
    asm volatile("ldmatrix.sync.aligned.m8n8.x4.shared.b16 {%0,%1,%2,%3}, [%4];"
                 : "=r"(r[0]), "=r"(r[1]), "=r"(r[2]), "=r"(r[3]) : "r"(addr));
}

__device__ __forceinline__ void mma16816(float* c, const uint32_t* a,
                                         const uint32_t* b) {
    asm volatile(
        "mma.sync.aligned.m16n8k16.row.col.f32.f16.f16.f32 "
        "{%0,%1,%2,%3}, {%4,%5,%6,%7}, {%8,%9}, {%0,%1,%2,%3};"
        : "+f"(c[0]), "+f"(c[1]), "+f"(c[2]), "+f"(c[3])
        : "r"(a[0]), "r"(a[1]), "r"(a[2]), "r"(a[3]), "r"(b[0]), "r"(b[1]));
}

// swizzled byte offset inside a 128-row x 32-col fp16 tile (64B rows)
__device__ __forceinline__ uint32_t swz(uint32_t row, uint32_t chunk) {
    return row * 64u + ((chunk ^ ((row >> 1) & 3u)) << 4);
}

__device__ __forceinline__ float lrelu(float v) {
    return (v >= 0.f) ? v : 0.01f * v;
}

// ======================= prep kernels ======================================

// g = fp16(node_conv(x, w)), x float32
__global__ void nodeconv_fp16(const float* __restrict__ x,
                              const float* __restrict__ w,   // [4, F]
                              __half* __restrict__ g,
                              int rows_out, int F)
{
    int idx = blockIdx.x * blockDim.x + threadIdx.x;
    int K4 = F >> 2;
    if (idx >= rows_out * K4) return;
    int r = idx / K4;
    int c = (idx - r * K4) << 2;

    float acc[4] = {0.f, 0.f, 0.f, 0.f};
#pragma unroll
    for (int p = 0; p < 4; ++p) {
        float4 xv = *(const float4*)(x + (size_t)(4 * r + p) * F + c);
        float4 wv = *(const float4*)(w + (size_t)p * F + c);
        acc[0] = fmaf(xv.x, wv.x, acc[0]);
        acc[1] = fmaf(xv.y, wv.y, acc[1]);
        acc[2] = fmaf(xv.z, wv.z, acc[2]);
        acc[3] = fmaf(xv.w, wv.w, acc[3]);
    }
    __align__(8) __half hv[4];
#pragma unroll
    for (int i = 0; i < 4; ++i) hv[i] = __float2half_rn(acc[i]);
    *(uint2*)(g + (size_t)r * F + c) = *(uint2*)hv;
}

// out[n,k] = fp16(W[k,n]), zero-padded
__global__ void transpose_fp16(const float* __restrict__ W,
                               __half* __restrict__ B,
                               int Kreal, int Kpad, int Nreal, int Npad)
{
    __shared__ float tile[32][33];
    int nb = blockIdx.x * 32, kb = blockIdx.y * 32;
    int tx = threadIdx.x, ty = threadIdx.y;  // (32, 8)
#pragma unroll
    for (int i = 0; i < 32; i += 8) {
        int k = kb + ty + i, n = nb + tx;
        tile[ty + i][tx] = (k < Kreal && n < Nreal) ? W[(size_t)k * Nreal + n] : 0.f;
    }
    __syncthreads();
#pragma unroll
    for (int i = 0; i < 32; i += 8) {
        int n = nb + ty + i, k = kb + tx;
        if (n < Npad && k < Kpad)
            B[(size_t)n * Kpad + k] = __float2half_rn(tile[tx][ty + i]);
    }
}

// ======================= fp16 mma.sync GEMM ================================
// EPI == 0: C float, C = lrelu(A @ B^T + bias)   (final output)
// EPI == 2: fused nodeconv: C (__half) gets
//           g2[r, col] = sum_p lrelu((A@B^T + bias)[4r+p, col]) * cw[p, col]
//           rows of C = M/4; pad cols (>= Nreal) written as 0.
// grid = (Npad/128, M/128), 128 threads (4 warps of 64x64), K % 32 == 0.

#define BK       32
#define STAGES   4
#define TILE_B   8192                   // one 128x32 fp16 tile
#define STAGE_B  (2 * TILE_B)           // A + B
#define SMEM_DYN (STAGES * STAGE_B)     // 65536

template <int EPI>
__global__ __launch_bounds__(128, 2)
void gemm_fp16(const __half* __restrict__ A,
               const __half* __restrict__ B,
               const float* __restrict__ bias,
               void* __restrict__ Cv,
               const float* __restrict__ cw,   // [4, Nreal] (EPI==2 only)
               int K, int Nreal, int ostride)
{
    extern __shared__ __align__(1024) char smem[];
    const uint32_t sb = smem_u32(smem);

    const int tid  = threadIdx.x;
    const int wid  = tid >> 5;
    const int lane = tid & 31;
    const int row0 = blockIdx.y * 128;
    const int col0 = blockIdx.x * 128;
    const int NC   = K / BK;

    const int warp_m = (wid & 1) * 64;     // 2 warps in M
    const int warp_n = (wid >> 1) * 64;    // 2 warps in N

    // ---- cp.async mapping: thread covers 4 chunks per 128x32 tile ----
    uint32_t ssw[4];
    int      srow[4];
#pragma unroll
    for (int q = 0; q < 4; ++q) {
        const int idx = tid + q * 128;      // 0..511
        srow[q] = idx >> 2;
        ssw[q]  = swz(idx >> 2, idx & 3);
    }
    const int schk = tid & 3;

    auto issue_stage = [&](int st, int kt) {
        const int kb = kt * BK + schk * 8;
        const uint32_t base = sb + st * STAGE_B;
#pragma unroll
        for (int q = 0; q < 4; ++q) {
            cp16(base + ssw[q],          A + (size_t)(row0 + srow[q]) * K + kb);
            cp16(base + TILE_B + ssw[q], B + (size_t)(col0 + srow[q]) * K + kb);
        }
        asm volatile("cp.async.commit_group;");
    };

    float acc[4][8][4];
#pragma unroll
    for (int mt = 0; mt < 4; ++mt)
#pragma unroll
        for (int nt = 0; nt < 8; ++nt)
#pragma unroll
            for (int q = 0; q < 4; ++q) acc[mt][nt][q] = 0.f;

    issue_stage(0, 0);
    issue_stage(1, 1);
    issue_stage(2, 2);

    // ldmatrix lane-dependent pieces
    const uint32_t a_lrow = lane & 15;
    const uint32_t a_lchk = lane >> 4;
    const uint32_t b_lrow = (lane & 7) + ((lane >> 4) << 3);
    const uint32_t b_lchk = (lane >> 3) & 1;

    for (int i = 0; i < NC; ++i) {
        asm volatile("cp.async.wait_group 2;");
        __syncthreads();
        if (i + 3 < NC) issue_stage((i + 3) & 3, i + 3);

        const uint32_t base = sb + (i & 3) * STAGE_B;

        // ---- load ALL B fragments (both ks halves) up front ----
        uint32_t bfr[2][8][2];
#pragma unroll
        for (int ks = 0; ks < 2; ++ks)
#pragma unroll
            for (int ntp = 0; ntp < 4; ++ntp)
                ldm_x4(&bfr[ks][ntp * 2][0],
                       base + TILE_B +
                       swz(warp_n + ntp * 16 + b_lrow, ks * 2 + b_lchk));

        // ---- A fragments: double-buffered one step ahead ----
        uint32_t afr[2][4];
        ldm_x4(afr[0], base + swz(warp_m + a_lrow, a_lchk));
#pragma unroll
        for (int ks = 0; ks < 2; ++ks) {
#pragma unroll
            for (int mt = 0; mt < 4; ++mt) {
                const int step = ks * 4 + mt;
                const int cur  = step & 1;
                if (step < 7) {
                    const int nmt = (mt + 1) & 3;
                    const int nks = ks + (mt == 3 ? 1 : 0);
                    ldm_x4(afr[cur ^ 1],
                           base + swz(warp_m + nmt * 16 + a_lrow,
                                      nks * 2 + a_lchk));
                }
#pragma unroll
                for (int nt = 0; nt < 8; ++nt)
                    mma16816(acc[mt][nt], afr[cur], bfr[ks][nt]);
            }
        }
        // stage-reuse ordering is provided by the top-of-loop barrier
    }

    // ---- epilogue ----
    const int erow = lane >> 2;          // 0..7
    const int ecol = (lane & 3) * 2;

    if constexpr (EPI == 0) {
        float* C = (float*)Cv;
#pragma unroll
        for (int mt = 0; mt < 4; ++mt) {
#pragma unroll
            for (int nt = 0; nt < 8; ++nt) {
                const int colg = col0 + warp_n + nt * 8 + ecol;
                if (colg >= Nreal) continue;
                const float bx = bias[colg], by = bias[colg + 1];
                const int rg0 = row0 + warp_m + mt * 16 + erow;
                float v0 = lrelu(acc[mt][nt][0] + bx);
                float v1 = lrelu(acc[mt][nt][1] + by);
                float v2 = lrelu(acc[mt][nt][2] + bx);
                float v3 = lrelu(acc[mt][nt][3] + by);
                *(float2*)(C + (size_t)rg0 * ostride + colg) =
                    make_float2(v0, v1);
                *(float2*)(C + (size_t)(rg0 + 8) * ostride + colg) =
                    make_float2(v2, v3);
            }
        }
    } else {
        // fused nodeconv2: reduce lrelu(h) over 4-row windows with weights
        // cw[p, col], p = row & 3 (== erow & 3 since row0+warp_m+mt*16 % 4 == 0)
        __half* C = (__half*)Cv;
        const int p = erow & 3;
        const bool writer = ((erow & 3) == 0);           // lanes 0-3, 16-19
        const int sub = (lane >> 4);                     // erow group 0 / 1
#pragma unroll
        for (int nt = 0; nt < 8; ++nt) {
            const int colg = col0 + warp_n + nt * 8 + ecol;
            float bx = 0.f, by = 0.f, cwx = 0.f, cwy = 0.f;
            if (colg < Nreal) {
                bx  = bias[colg];
                by  = bias[colg + 1];
                cwx = cw[(size_t)p * Nreal + colg];
                cwy = cw[(size_t)p * Nreal + colg + 1];
            }
#pragma unroll
            for (int mt = 0; mt < 4; ++mt) {
                float s0 = lrelu(acc[mt][nt][0] + bx) * cwx;
                float s1 = lrelu(acc[mt][nt][1] + by) * cwy;
                float s2 = lrelu(acc[mt][nt][2] + bx) * cwx;
                float s3 = lrelu(acc[mt][nt][3] + by) * cwy;
                // sum over erow bits 0,1 (lane bits 2,3) = 4-row windows
                s0 += __shfl_xor_sync(0xffffffffu, s0, 4);
                s0 += __shfl_xor_sync(0xffffffffu, s0, 8);
                s1 += __shfl_xor_sync(0xffffffffu, s1, 4);
                s1 += __shfl_xor_sync(0xffffffffu, s1, 8);
                s2 += __shfl_xor_sync(0xffffffffu, s2, 4);
                s2 += __shfl_xor_sync(0xffffffffu, s2, 8);
                s3 += __shfl_xor_sync(0xffffffffu, s3, 4);
                s3 += __shfl_xor_sync(0xffffffffu, s3, 8);
                if (writer) {
                    const int g2r = ((row0 + warp_m + mt * 16) >> 2) + sub;
                    *(__half2*)(C + (size_t)g2r * ostride + colg) =
                        __floats2half2_rn(s0, s1);
                    *(__half2*)(C + (size_t)(g2r + 2) * ostride + colg) =
                        __floats2half2_rn(s2, s3);
                }
            }
        }
    }
}

// ======================= launch ============================================

extern "C" void kernel_launch(void* const* d_in, const int* in_sizes, int n_in,
                              void* d_out, int out_size)
{
    const float* x       = (const float*)d_in[0];   // [64,512,2048]
    const float* conv1_w = (const float*)d_in[1];   // [4,2048]
    const float* prop1_W = (const float*)d_in[4];   // [2048,1100]
    const float* prop1_B = (const float*)d_in[5];   // [1100]
    const float* conv2_w = (const float*)d_in[6];   // [4,1100]
    const float* prop2_W = (const float*)d_in[9];   // [1100,512]
    const float* prop2_B = (const float*)d_in[10];  // [512]

    __half *g1, *g2, *w1, *w2;
    cudaGetSymbolAddress((void**)&g1, g_g1);
    cudaGetSymbolAddress((void**)&g2, g_g2);
    cudaGetSymbolAddress((void**)&w1, g_w1);
    cudaGetSymbolAddress((void**)&w2, g_w2);

    cudaFuncSetAttribute((void*)gemm_fp16<2>,
                         cudaFuncAttributeMaxDynamicSharedMemorySize, SMEM_DYN);
    cudaFuncSetAttribute((void*)gemm_fp16<0>,
                         cudaFuncAttributeMaxDynamicSharedMemorySize, SMEM_DYN);

    // weight transforms
    {
        dim3 blk(32, 8);
        transpose_fp16<<<dim3(N1P / 32, F1 / 32), blk>>>(prop1_W, w1,
                                                         F1, F1, N1R, N1P);
        transpose_fp16<<<dim3(N2 / 32, K2P / 32), blk>>>(prop2_W, w2,
                                                         N1R, K2P, N2, N2);
    }

    // stage 1: nodeconv1, then GEMM1 with fused nodeconv2 -> writes g2
    {
        int total = ROWS1 * (F1 / 4);
        nodeconv_fp16<<<(total + 255) / 256, 256>>>(x, conv1_w, g1, ROWS1, F1);
        gemm_fp16<2><<<dim3(N1P / 128, ROWS1 / 128), 128, SMEM_DYN>>>(
            g1, w1, prop1_B, g2, conv2_w, F1, N1R, K2P);
    }

    // stage 2: GEMM2 -> final output
    {
        gemm_fp16<0><<<dim3(N2 / 128, ROWS2 / 128), 128, SMEM_DYN>>>(
            g2, w2, prop2_B, d_out, nullptr, K2P, N2, N2);
    }
}

// round 11
// speedup vs baseline: 1.1057x; 1.0482x over previous
#include <cuda_runtime.h>
#include <cuda_fp16.h>
#include <cstdint>

// ---------------------------------------------------------------------------
// DCGN collapses (normalized adjacency == identity) to:
//   g1 = node_conv(x, conv1_w)                [8192, 2048]
//   h  = lrelu(g1 @ prop1_W + prop1_B)        [8192, 1100]  (N pad -> 1152)
//   g2 = node_conv(h, conv2_w)                [2048, 1100]  (K pad -> 1152)
//   out= lrelu(g2 @ prop2_W + prop2_B)        [2048, 512]
// fp16 x fp16 mma.sync GEMMs (measured error budget ~3e-5).
// GEMM1 (<EPI=2,MROWS=128>): nodeconv2 fused in epilogue (h never exists).
// GEMM2 (<EPI=0,MROWS=64>): half-height CTAs -> 128 CTAs, better SM fill.
// ---------------------------------------------------------------------------

#define ROWS1 8192
#define F1    2048
#define N1R   1100
#define N1P   1152
#define ROWS2 2048
#define K2P   1152
#define N2    512

__device__ __half g_g1[(size_t)ROWS1 * F1];
__device__ __half g_g2[(size_t)ROWS2 * K2P];
__device__ __half g_w1[(size_t)N1P * F1];
__device__ __half g_w2[(size_t)N2 * K2P];

// ===================== PTX helpers ========================

__device__ __forceinline__ uint32_t smem_u32(const void* p) {
    uint32_t a;
    asm("{ .reg .u64 t; cvta.to.shared.u64 t, %1; cvt.u32.u64 %0, t; }"
        : "=r"(a) : "l"(p));
    return a;
}

__device__ __forceinline__ void cp16(uint32_t dst, const void* src) {
    asm volatile("cp.async.cg.shared.global [%0], [%1], 16;"
                 :: "r"(dst), "l"(src));
}

__device__ __forceinline__ void ldm_x4(uint32_t* r, uint32_t addr) {
    asm volatile("ldmatrix.sync.aligned.m8n8.x4.shared.b16 {%0,%1,%2,%3}, [%4];"
                 : "=r"(r[0]), "=r"(r[1]), "=r"(r[2]), "=r"(r[3]) : "r"(addr));
}

__device__ __forceinline__ void mma16816(float* c, const uint32_t* a,
                                         const uint32_t* b) {
    asm volatile(
        "mma.sync.aligned.m16n8k16.row.col.f32.f16.f16.f32 "
        "{%0,%1,%2,%3}, {%4,%5,%6,%7}, {%8,%9}, {%0,%1,%2,%3};"
        : "+f"(c[0]), "+f"(c[1]), "+f"(c[2]), "+f"(c[3])
        : "r"(a[0]), "r"(a[1]), "r"(a[2]), "r"(a[3]), "r"(b[0]), "r"(b[1]));
}

// swizzled byte offset inside an (up to 128)-row x 32-col fp16 tile (64B rows)
__device__ __forceinline__ uint32_t swz(uint32_t row, uint32_t chunk) {
    return row * 64u + ((chunk ^ ((row >> 1) & 3u)) << 4);
}

__device__ __forceinline__ float lrelu(float v) {
    return (v >= 0.f) ? v : 0.01f * v;
}

// ======================= prep kernels ======================================

// g = fp16(node_conv(x, w)), x float32
__global__ void nodeconv_fp16(const float* __restrict__ x,
                              const float* __restrict__ w,   // [4, F]
                              __half* __restrict__ g,
                              int rows_out, int F)
{
    int idx = blockIdx.x * blockDim.x + threadIdx.x;
    int K4 = F >> 2;
    if (idx >= rows_out * K4) return;
    int r = idx / K4;
    int c = (idx - r * K4) << 2;

    float acc[4] = {0.f, 0.f, 0.f, 0.f};
#pragma unroll
    for (int p = 0; p < 4; ++p) {
        float4 xv = *(const float4*)(x + (size_t)(4 * r + p) * F + c);
        float4 wv = *(const float4*)(w + (size_t)p * F + c);
        acc[0] = fmaf(xv.x, wv.x, acc[0]);
        acc[1] = fmaf(xv.y, wv.y, acc[1]);
        acc[2] = fmaf(xv.z, wv.z, acc[2]);
        acc[3] = fmaf(xv.w, wv.w, acc[3]);
    }
    __align__(8) __half hv[4];
#pragma unroll
    for (int i = 0; i < 4; ++i) hv[i] = __float2half_rn(acc[i]);
    *(uint2*)(g + (size_t)r * F + c) = *(uint2*)hv;
}

// merged transpose for both weight matrices: out[n,k] = fp16(W[k,n]), padded.
// blocks [0, n1blocks) -> tensor 1; the rest -> tensor 2.
__global__ void transpose2_fp16(const float* __restrict__ W1,
                                __half* __restrict__ B1,
                                int K1real, int K1pad, int N1real, int N1pad,
                                int n1bx, int n1blocks,
                                const float* __restrict__ W2,
                                __half* __restrict__ B2,
                                int K2real, int K2pad, int N2real, int N2pad,
                                int n2bx)
{
    __shared__ float tile[32][33];
    const float* W; __half* B;
    int Kreal, Kpad, Nreal, Npad, bxg;
    int b = blockIdx.x;
    if (b < n1blocks) {
        W = W1; B = B1; Kreal = K1real; Kpad = K1pad;
        Nreal = N1real; Npad = N1pad; bxg = b % n1bx;  b /= n1bx;
    } else {
        int b2 = b - n1blocks;
        W = W2; B = B2; Kreal = K2real; Kpad = K2pad;
        Nreal = N2real; Npad = N2pad; bxg = b2 % n2bx; b = b2 / n2bx;
    }
    int nb = bxg * 32, kb = b * 32;
    int tx = threadIdx.x, ty = threadIdx.y;  // (32, 8)
#pragma unroll
    for (int i = 0; i < 32; i += 8) {
        int k = kb + ty + i, n = nb + tx;
        tile[ty + i][tx] = (k < Kreal && n < Nreal) ? W[(size_t)k * Nreal + n] : 0.f;
    }
    __syncthreads();
#pragma unroll
    for (int i = 0; i < 32; i += 8) {
        int n = nb + ty + i, k = kb + tx;
        if (n < Npad && k < Kpad)
            B[(size_t)n * Kpad + k] = __float2half_rn(tile[tx][ty + i]);
    }
}

// ======================= fp16 mma.sync GEMM ================================
// CTA tile: MROWS x 128, 128 threads (4 warps of (MROWS/2) x 64).
// EPI == 0: C float, C = lrelu(A @ B^T + bias)
// EPI == 2: fused nodeconv epilogue (MROWS==128 only):
//           g2[r,col] = sum_p lrelu((A@B^T+bias)[4r+p,col]) * cw[p,col]
// grid = (Npad/128, M/MROWS), K % 32 == 0, K/32 >= 4.

#define BK       32
#define STAGES   4
#define TILE_BB  8192                   // B tile: 128x32 fp16

template <int EPI, int MROWS>
__global__ __launch_bounds__(128, 2)
void gemm_fp16(const __half* __restrict__ A,
               const __half* __restrict__ B,
               const float* __restrict__ bias,
               void* __restrict__ Cv,
               const float* __restrict__ cw,   // [4, Nreal] (EPI==2 only)
               int K, int Nreal, int ostride)
{
    constexpr int MTN     = MROWS / 32;          // m-tiles per warp
    constexpr int TILE_A  = MROWS * 64;          // A tile bytes
    constexpr int STAGE_B = TILE_A + TILE_BB;
    constexpr int QA      = (MROWS * 4) / 128;   // A 16B-chunks per thread

    extern __shared__ __align__(1024) char smem[];
    const uint32_t sb = smem_u32(smem);

    const int tid  = threadIdx.x;
    const int wid  = tid >> 5;
    const int lane = tid & 31;
    const int row0 = blockIdx.y * MROWS;
    const int col0 = blockIdx.x * 128;
    const int NC   = K / BK;

    const int warp_m = (wid & 1) * (MROWS / 2);
    const int warp_n = (wid >> 1) * 64;

    // ---- cp.async mapping ----
    uint32_t sswA[QA]; int srowA[QA];
#pragma unroll
    for (int q = 0; q < QA; ++q) {
        const int idx = tid + q * 128;
        srowA[q] = idx >> 2;
        sswA[q]  = swz(idx >> 2, idx & 3);
    }
    uint32_t sswB[4]; int srowB[4];
#pragma unroll
    for (int q = 0; q < 4; ++q) {
        const int idx = tid + q * 128;
        srowB[q] = idx >> 2;
        sswB[q]  = swz(idx >> 2, idx & 3);
    }
    const int schk = tid & 3;

    auto issue_stage = [&](int st, int kt) {
        const int kb = kt * BK + schk * 8;
        const uint32_t base = sb + st * STAGE_B;
#pragma unroll
        for (int q = 0; q < QA; ++q)
            cp16(base + sswA[q], A + (size_t)(row0 + srowA[q]) * K + kb);
#pragma unroll
        for (int q = 0; q < 4; ++q)
            cp16(base + TILE_A + sswB[q],
                 B + (size_t)(col0 + srowB[q]) * K + kb);
        asm volatile("cp.async.commit_group;");
    };

    float acc[MTN][8][4];
#pragma unroll
    for (int mt = 0; mt < MTN; ++mt)
#pragma unroll
        for (int nt = 0; nt < 8; ++nt)
#pragma unroll
            for (int q = 0; q < 4; ++q) acc[mt][nt][q] = 0.f;

    issue_stage(0, 0);
    issue_stage(1, 1);
    issue_stage(2, 2);

    // ldmatrix lane-dependent pieces
    const uint32_t a_lrow = lane & 15;
    const uint32_t a_lchk = lane >> 4;
    const uint32_t b_lrow = (lane & 7) + ((lane >> 4) << 3);
    const uint32_t b_lchk = (lane >> 3) & 1;

    for (int i = 0; i < NC; ++i) {
        asm volatile("cp.async.wait_group 2;");
        __syncthreads();
        if (i + 3 < NC) issue_stage((i + 3) & 3, i + 3);

        const uint32_t base = sb + (i & 3) * STAGE_B;

        // ---- load ALL B fragments (both ks halves) up front ----
        uint32_t bfr[2][8][2];
#pragma unroll
        for (int ks = 0; ks < 2; ++ks)
#pragma unroll
            for (int ntp = 0; ntp < 4; ++ntp)
                ldm_x4(&bfr[ks][ntp * 2][0],
                       base + TILE_A +
                       swz(warp_n + ntp * 16 + b_lrow, ks * 2 + b_lchk));

        // ---- A fragments: double-buffered one step ahead ----
        uint32_t afr[2][4];
        ldm_x4(afr[0], base + swz(warp_m + a_lrow, a_lchk));
#pragma unroll
        for (int ks = 0; ks < 2; ++ks) {
#pragma unroll
            for (int mt = 0; mt < MTN; ++mt) {
                const int step = ks * MTN + mt;
                const int cur  = step & 1;
                if (step < 2 * MTN - 1) {
                    const int nmt = (mt + 1) % MTN;
                    const int nks = ks + (mt == MTN - 1 ? 1 : 0);
                    ldm_x4(afr[cur ^ 1],
                           base + swz(warp_m + nmt * 16 + a_lrow,
                                      nks * 2 + a_lchk));
                }
#pragma unroll
                for (int nt = 0; nt < 8; ++nt)
                    mma16816(acc[mt][nt], afr[cur], bfr[ks][nt]);
            }
        }
        // stage-reuse ordering is provided by the top-of-loop barrier
    }

    // ---- epilogue ----
    const int erow = lane >> 2;          // 0..7
    const int ecol = (lane & 3) * 2;

    if constexpr (EPI == 0) {
        float* C = (float*)Cv;
#pragma unroll
        for (int mt = 0; mt < MTN; ++mt) {
#pragma unroll
            for (int nt = 0; nt < 8; ++nt) {
                const int colg = col0 + warp_n + nt * 8 + ecol;
                if (colg >= Nreal) continue;
                const float bx = bias[colg], by = bias[colg + 1];
                const int rg0 = row0 + warp_m + mt * 16 + erow;
                float v0 = lrelu(acc[mt][nt][0] + bx);
                float v1 = lrelu(acc[mt][nt][1] + by);
                float v2 = lrelu(acc[mt][nt][2] + bx);
                float v3 = lrelu(acc[mt][nt][3] + by);
                *(float2*)(C + (size_t)rg0 * ostride + colg) =
                    make_float2(v0, v1);
                *(float2*)(C + (size_t)(rg0 + 8) * ostride + colg) =
                    make_float2(v2, v3);
            }
        }
    } else {
        // fused nodeconv2: reduce lrelu(h) over 4-row windows with weights
        // cw[p, col], p = erow & 3 (row0+warp_m+mt*16 is a multiple of 4)
        __half* C = (__half*)Cv;
        const int p = erow & 3;
        const bool writer = ((erow & 3) == 0);
        const int sub = (lane >> 4);
#pragma unroll
        for (int nt = 0; nt < 8; ++nt) {
            const int colg = col0 + warp_n + nt * 8 + ecol;
            float bx = 0.f, by = 0.f, cwx = 0.f, cwy = 0.f;
            if (colg < Nreal) {
                bx  = bias[colg];
                by  = bias[colg + 1];
                cwx = cw[(size_t)p * Nreal + colg];
                cwy = cw[(size_t)p * Nreal + colg + 1];
            }
#pragma unroll
            for (int mt = 0; mt < MTN; ++mt) {
                float s0 = lrelu(acc[mt][nt][0] + bx) * cwx;
                float s1 = lrelu(acc[mt][nt][1] + by) * cwy;
                float s2 = lrelu(acc[mt][nt][2] + bx) * cwx;
                float s3 = lrelu(acc[mt][nt][3] + by) * cwy;
                s0 += __shfl_xor_sync(0xffffffffu, s0, 4);
                s0 += __shfl_xor_sync(0xffffffffu, s0, 8);
                s1 += __shfl_xor_sync(0xffffffffu, s1, 4);
                s1 += __shfl_xor_sync(0xffffffffu, s1, 8);
                s2 += __shfl_xor_sync(0xffffffffu, s2, 4);
                s2 += __shfl_xor_sync(0xffffffffu, s2, 8);
                s3 += __shfl_xor_sync(0xffffffffu, s3, 4);
                s3 += __shfl_xor_sync(0xffffffffu, s3, 8);
                if (writer) {
                    const int g2r = ((row0 + warp_m + mt * 16) >> 2) + sub;
                    *(__half2*)(C + (size_t)g2r * ostride + colg) =
                        __floats2half2_rn(s0, s1);
                    *(__half2*)(C + (size_t)(g2r + 2) * ostride + colg) =
                        __floats2half2_rn(s2, s3);
                }
            }
        }
    }
}

// ======================= launch ============================================

extern "C" void kernel_launch(void* const* d_in, const int* in_sizes, int n_in,
                              void* d_out, int out_size)
{
    const float* x       = (const float*)d_in[0];   // [64,512,2048]
    const float* conv1_w = (const float*)d_in[1];   // [4,2048]
    const float* prop1_W = (const float*)d_in[4];   // [2048,1100]
    const float* prop1_B = (const float*)d_in[5];   // [1100]
    const float* conv2_w = (const float*)d_in[6];   // [4,1100]
    const float* prop2_W = (const float*)d_in[9];   // [1100,512]
    const float* prop2_B = (const float*)d_in[10];  // [512]

    __half *g1, *g2, *w1, *w2;
    cudaGetSymbolAddress((void**)&g1, g_g1);
    cudaGetSymbolAddress((void**)&g2, g_g2);
    cudaGetSymbolAddress((void**)&w1, g_w1);
    cudaGetSymbolAddress((void**)&w2, g_w2);

    const int SMEM1 = STAGES * (128 * 64 + TILE_BB);   // 65536
    const int SMEM2 = STAGES * (64 * 64 + TILE_BB);    // 49152
    cudaFuncSetAttribute((void*)gemm_fp16<2, 128>,
                         cudaFuncAttributeMaxDynamicSharedMemorySize, SMEM1);
    cudaFuncSetAttribute((void*)gemm_fp16<0, 64>,
                         cudaFuncAttributeMaxDynamicSharedMemorySize, SMEM2);

    // merged weight transposes (w1: 36x64 blocks, w2: 16x36 blocks)
    {
        const int n1bx = N1P / 32, n1blocks = n1bx * (F1 / 32);   // 36*64
        const int n2bx = N2 / 32,  n2blocks = n2bx * (K2P / 32);  // 16*36
        transpose2_fp16<<<n1blocks + n2blocks, dim3(32, 8)>>>(
            prop1_W, w1, F1, F1, N1R, N1P, n1bx, n1blocks,
            prop2_W, w2, N1R, K2P, N2, N2, n2bx);
    }

    // stage 1: nodeconv1, then GEMM1 with fused nodeconv2 -> writes g2
    {
        int total = ROWS1 * (F1 / 4);
        nodeconv_fp16<<<(total + 255) / 256, 256>>>(x, conv1_w, g1, ROWS1, F1);
        gemm_fp16<2, 128><<<dim3(N1P / 128, ROWS1 / 128), 128, SMEM1>>>(
            g1, w1, prop1_B, g2, conv2_w, F1, N1R, K2P);
    }

    // stage 2: GEMM2 -> final output (64-row CTAs, 128 CTAs for SM fill)
    {
        gemm_fp16<0, 64><<<dim3(N2 / 128, ROWS2 / 64), 128, SMEM2>>>(
            g2, w2, prop2_B, d_out, nullptr, K2P, N2, N2);
    }
}